// round 5
// baseline (speedup 1.0000x reference)
#include <cuda_runtime.h>
#include <cstdint>

#define S_LEN 2048
#define NH    16
#define HD    64
#define NTHR  256
#define SCALE 0.1875f   // 1.5 / sqrt(64)

#define QS 68
#define KS 68
#define VS 72
#define AS 68
// Qs[64*68] | K[2][64*68] | V[2][64*72] | At[64*68] | Rem[64]
#define SMEM_FLOATS (64*QS + 2*64*KS + 2*64*VS + 64*AS + 64)

__device__ __forceinline__ uint32_t f2tf(float x) {
    uint32_t r; asm("cvt.rna.tf32.f32 %0, %1;" : "=r"(r) : "f"(x)); return r;
}

__device__ __forceinline__ void mma_tf32(float& d0, float& d1, float& d2, float& d3,
                                         uint32_t a0, uint32_t a1, uint32_t a2, uint32_t a3,
                                         uint32_t b0, uint32_t b1) {
    asm volatile("mma.sync.aligned.m16n8k8.row.col.f32.tf32.tf32.f32 "
                 "{%0,%1,%2,%3}, {%4,%5,%6,%7}, {%8,%9}, {%0,%1,%2,%3};"
                 : "+f"(d0), "+f"(d1), "+f"(d2), "+f"(d3)
                 : "r"(a0), "r"(a1), "r"(a2), "r"(a3), "r"(b0), "r"(b1));
}

__device__ __forceinline__ void sts_tf4(float* dst, float4 v) {
    dst[0] = __uint_as_float(f2tf(v.x));
    dst[1] = __uint_as_float(f2tf(v.y));
    dst[2] = __uint_as_float(f2tf(v.z));
    dst[3] = __uint_as_float(f2tf(v.w));
}

__global__ void __launch_bounds__(NTHR, 2)
sb_attn_kernel(const float* __restrict__ qkv, float* __restrict__ out)
{
    extern __shared__ float smem[];
    float* Qs   = smem;                     // [64][68] tf32, pre-scaled
    float* Ksb  = Qs  + 64 * QS;            // [2][64][68] tf32
    float* Vsb  = Ksb + 2 * 64 * KS;        // [2][64][72] tf32
    float* At   = Vsb + 2 * 64 * VS;        // [64][68]
    float* RemS = At  + 64 * AS;            // [64]

    const int tt   = (int)gridDim.x - 1 - (int)blockIdx.x;  // heavy tiles first
    const int h    = blockIdx.y;
    const int b    = blockIdx.z;
    const int tid  = threadIdx.x;
    const int warp = tid >> 5;
    const int lane = tid & 31;
    const int t0   = tt * 64;

    // mma partition (R2-verified): warp owns rows m0..m0+15, cols ng*32..+31
    const int mb = warp & 3;
    const int ng = warp >> 2;
    const int m0 = mb * 16;
    const int gp = lane >> 2;
    const int qd = lane & 3;

    // per-thread staging coordinates (4 chunks of 64x16-float4 tile)
    int srow[4], scol[4];
    #pragma unroll
    for (int p = 0; p < 4; p++) {
        int i = tid + p * NTHR;
        srow[p] = i >> 4;
        scol[p] = (i & 15) * 4;
    }

    // ---- Prologue: Q (scaled) + diagonal K/V tile, synchronous (R2-style) ----
    #pragma unroll
    for (int p = 0; p < 4; p++) {
        const int r = srow[p], c = scol[p];
        const float* qp = qkv + (((size_t)b * S_LEN + (t0 + r)) * 3 + 0) * (NH * HD) + h * HD + c;
        float4 v = *(const float4*)qp;
        v.x *= SCALE; v.y *= SCALE; v.z *= SCALE; v.w *= SCALE;
        sts_tf4(&Qs[r * QS + c], v);
    }
    {
        float* Kb = Ksb + (tt & 1) * (64 * KS);
        float* Vb = Vsb + (tt & 1) * (64 * VS);
        #pragma unroll
        for (int p = 0; p < 4; p++) {
            const int r = srow[p], c = scol[p];
            const float* kp = qkv + (((size_t)b * S_LEN + (t0 + r)) * 3 + 1) * (NH * HD) + h * HD + c;
            sts_tf4(&Kb[r * KS + c], *(const float4*)kp);
            sts_tf4(&Vb[r * VS + c], *(const float4*)(kp + NH * HD));
        }
    }

    float run[8];
    float o[4][4];
    #pragma unroll
    for (int r = 0; r < 8; r++) run[r] = 0.f;
    #pragma unroll
    for (int j = 0; j < 4; j++)
        #pragma unroll
        for (int c = 0; c < 4; c++) o[j][c] = 0.f;

    // ---- Key tiles from diagonal down to 0 ----
    for (int kt = tt; kt >= 0; --kt) {
        __syncthreads();   // B1: buf(kt&1) fully written; At reuse from prev tile safe

        const int s0 = kt * 64;
        const float* Kb = Ksb + (kt & 1) * (64 * KS);
        const float* Vb = Vsb + (kt & 1) * (64 * VS);
        float* Kn = Ksb + ((kt - 1) & 1) * (64 * KS);
        float* Vn = Vsb + ((kt - 1) & 1) * (64 * VS);

        // issue next tile's K loads now — latency hidden behind QK + scan
        float4 kreg[4];
        if (kt > 0) {
            const int s0n = (kt - 1) * 64;
            #pragma unroll
            for (int p = 0; p < 4; p++) {
                const float* kp = qkv + (((size_t)b * S_LEN + (s0n + srow[p])) * 3 + 1) * (NH * HD)
                                      + h * HD + scol[p];
                kreg[p] = *(const float4*)kp;
            }
        }

        // ---- QK^T (R2-verified) ----
        float d[4][4];
        #pragma unroll
        for (int j = 0; j < 4; j++)
            #pragma unroll
            for (int c = 0; c < 4; c++) d[j][c] = 0.f;

        #pragma unroll
        for (int ks = 0; ks < 8; ks++) {
            const int kc = ks * 8;
            uint32_t a0 = __float_as_uint(Qs[(m0 + gp)     * QS + kc + qd]);
            uint32_t a1 = __float_as_uint(Qs[(m0 + gp + 8) * QS + kc + qd]);
            uint32_t a2 = __float_as_uint(Qs[(m0 + gp)     * QS + kc + qd + 4]);
            uint32_t a3 = __float_as_uint(Qs[(m0 + gp + 8) * QS + kc + qd + 4]);
            #pragma unroll
            for (int j = 0; j < 4; j++) {
                const int n0 = ng * 32 + j * 8;
                uint32_t b0 = __float_as_uint(Kb[(n0 + gp) * KS + kc + qd]);
                uint32_t b1 = __float_as_uint(Kb[(n0 + gp) * KS + kc + qd + 4]);
                mma_tf32(d[j][0], d[j][1], d[j][2], d[j][3], a0, a1, a2, a3, b0, b1);
            }
        }
        #pragma unroll
        for (int j = 0; j < 4; j++) {
            const int n0 = ng * 32 + j * 8;
            *(float2*)&At[(m0 + gp)     * AS + n0 + 2 * qd] = make_float2(d[j][0], d[j][1]);
            *(float2*)&At[(m0 + gp + 8) * AS + n0 + 2 * qd] = make_float2(d[j][2], d[j][3]);
        }
        __syncthreads();   // B2

        // ---- Stick-breaking scan (R2-verified, verbatim) ----
        #pragma unroll
        for (int r = 0; r < 8; r++) {
            const int row = warp * 8 + r;
            const int tg  = t0 + row;
            const float x0 = At[row * AS + lane];
            const float x1 = At[row * AS + lane + 32];
            const bool mm0 = (s0 + lane)      < tg;
            const bool mm1 = (s0 + lane + 32) < tg;
            float p0 = mm0 ? (fmaxf(x0, 0.f) + __logf(1.f + __expf(-fabsf(x0)))) : 0.f;
            float p1 = mm1 ? (fmaxf(x1, 0.f) + __logf(1.f + __expf(-fabsf(x1)))) : 0.f;

            float i0 = p0, i1 = p1;
            #pragma unroll
            for (int off = 1; off < 32; off <<= 1) {
                float u0 = __shfl_down_sync(0xffffffffu, i0, off);
                float u1 = __shfl_down_sync(0xffffffffu, i1, off);
                if (lane + off < 32) { i0 += u0; i1 += u1; }
            }
            const float tot0 = __shfl_sync(0xffffffffu, i0, 0);
            const float tot1 = __shfl_sync(0xffffffffu, i1, 0);
            const float ex1  = i1 - p1;
            const float ex0  = (i0 - p0) + tot1;
            const float base = run[r];
            const float att0 = mm0 ? __expf(x0 - p0 - base - ex0) : 0.f;
            const float att1 = mm1 ? __expf(x1 - p1 - base - ex1) : 0.f;
            At[row * AS + lane]      = __uint_as_float(f2tf(att0));
            At[row * AS + lane + 32] = __uint_as_float(f2tf(att1));
            run[r] = base + tot0 + tot1;
        }
        __syncthreads();   // B3

        // store prefetched K to idle buffer; issue V loads (hidden behind A.V)
        float4 vreg[4];
        if (kt > 0) {
            #pragma unroll
            for (int p = 0; p < 4; p++)
                sts_tf4(&Kn[srow[p] * KS + scol[p]], kreg[p]);
            const int s0n = (kt - 1) * 64;
            #pragma unroll
            for (int p = 0; p < 4; p++) {
                const float* vp = qkv + (((size_t)b * S_LEN + (s0n + srow[p])) * 3 + 2) * (NH * HD)
                                      + h * HD + scol[p];
                vreg[p] = *(const float4*)vp;
            }
        }

        // ---- A.V (R2-verified) ----
        #pragma unroll
        for (int ks = 0; ks < 8; ks++) {
            const int kc = ks * 8;
            uint32_t a0 = __float_as_uint(At[(m0 + gp)     * AS + kc + qd]);
            uint32_t a1 = __float_as_uint(At[(m0 + gp + 8) * AS + kc + qd]);
            uint32_t a2 = __float_as_uint(At[(m0 + gp)     * AS + kc + qd + 4]);
            uint32_t a3 = __float_as_uint(At[(m0 + gp + 8) * AS + kc + qd + 4]);
            #pragma unroll
            for (int j = 0; j < 4; j++) {
                const int n0 = ng * 32 + j * 8;
                uint32_t b0 = __float_as_uint(Vb[(kc + qd)     * VS + n0 + gp]);
                uint32_t b1 = __float_as_uint(Vb[(kc + qd + 4) * VS + n0 + gp]);
                mma_tf32(o[j][0], o[j][1], o[j][2], o[j][3], a0, a1, a2, a3, b0, b1);
            }
        }

        if (kt > 0) {
            #pragma unroll
            for (int p = 0; p < 4; p++)
                sts_tf4(&Vn[srow[p] * VS + scol[p]], vreg[p]);
        }
    }

    // ---- Remainder handoff + epilogue (R2-verified) ----
    if (lane == 0) {
        #pragma unroll
        for (int r = 0; r < 8; r++) RemS[warp * 8 + r] = __expf(-run[r]);
    }
    __syncthreads();

    const float rema = RemS[m0 + gp];
    const float remb = RemS[m0 + gp + 8];
    const int ra = t0 + m0 + gp;
    const int rb = ra + 8;
    #pragma unroll
    for (int j = 0; j < 4; j++) {
        const int n0 = ng * 32 + j * 8 + 2 * qd;
        const float* vpa = qkv + (((size_t)b * S_LEN + ra) * 3 + 2) * (NH * HD) + h * HD + n0;
        const float* vpb = qkv + (((size_t)b * S_LEN + rb) * 3 + 2) * (NH * HD) + h * HD + n0;
        float2 va = *(const float2*)vpa;
        float2 vb = *(const float2*)vpb;
        float2 oa = make_float2(o[j][0] + rema * va.x, o[j][1] + rema * va.y);
        float2 ob = make_float2(o[j][2] + remb * vb.x, o[j][3] + remb * vb.y);
        *(float2*)(out + (((size_t)b * S_LEN + ra) * NH + h) * HD + n0) = oa;
        *(float2*)(out + (((size_t)b * S_LEN + rb) * NH + h) * HD + n0) = ob;
    }
}

extern "C" void kernel_launch(void* const* d_in, const int* in_sizes, int n_in,
                              void* d_out, int out_size)
{
    const float* qkv = (const float*)d_in[0];
    float* out = (float*)d_out;

    cudaFuncSetAttribute(sb_attn_kernel,
                         cudaFuncAttributeMaxDynamicSharedMemorySize,
                         SMEM_FLOATS * sizeof(float));

    dim3 grid(S_LEN / 64, NH, 2);   // (32, 16, 2)
    sb_attn_kernel<<<grid, NTHR, SMEM_FLOATS * sizeof(float)>>>(qkv, out);
}

// round 6
// speedup vs baseline: 1.9030x; 1.9030x over previous
#include <cuda_runtime.h>
#include <cstdint>

#define S_LEN 2048
#define NH    16
#define HD    64
#define NTHR  128
#define SCALE 0.1875f   // 1.5 / sqrt(64)

#define QS 68
#define KS 68
#define VS 72
#define AS 68
// Qs[64*68] | Ks[64*68] | Vs[64*72] | At[64*68]
#define SMEM_FLOATS (64*QS + 64*KS + 64*VS + 64*AS)

__device__ __forceinline__ uint32_t f2tf(float x) {
    uint32_t r; asm("cvt.rna.tf32.f32 %0, %1;" : "=r"(r) : "f"(x)); return r;
}

__device__ __forceinline__ void mma_tf32(float& d0, float& d1, float& d2, float& d3,
                                         uint32_t a0, uint32_t a1, uint32_t a2, uint32_t a3,
                                         uint32_t b0, uint32_t b1) {
    asm volatile("mma.sync.aligned.m16n8k8.row.col.f32.tf32.tf32.f32 "
                 "{%0,%1,%2,%3}, {%4,%5,%6,%7}, {%8,%9}, {%0,%1,%2,%3};"
                 : "+f"(d0), "+f"(d1), "+f"(d2), "+f"(d3)
                 : "r"(a0), "r"(a1), "r"(a2), "r"(a3), "r"(b0), "r"(b1));
}

__device__ __forceinline__ void sts_tf4(float* dst, float4 v) {
    dst[0] = __uint_as_float(f2tf(v.x));
    dst[1] = __uint_as_float(f2tf(v.y));
    dst[2] = __uint_as_float(f2tf(v.z));
    dst[3] = __uint_as_float(f2tf(v.w));
}

__device__ __forceinline__ float softplus_f(float x) {
    return fmaxf(x, 0.f) + __logf(1.f + __expf(-fabsf(x)));
}

__global__ void __launch_bounds__(NTHR, 3)
sb_attn_kernel(const float* __restrict__ qkv, float* __restrict__ out)
{
    extern __shared__ float smem[];
    float* Qs = smem;                 // [64][68] tf32 (unscaled)
    float* Ks = Qs + 64 * QS;         // [64][68] tf32
    float* Vs = Ks + 64 * KS;         // [64][72] tf32
    float* At = Vs + 64 * VS;         // [64][68] att (tf32 bits), per-warp private rows

    const int tt   = (int)gridDim.x - 1 - (int)blockIdx.x;  // heavy tiles first
    const int h    = blockIdx.y;
    const int b    = blockIdx.z;
    const int tid  = threadIdx.x;
    const int warp = tid >> 5;
    const int lane = tid & 31;
    const int gp   = lane >> 2;   // 0..7
    const int qd   = lane & 3;    // 0..3
    const int m0   = warp * 16;   // warp owns rows m0..m0+15, ALL 64 cols
    const int t0   = tt * 64;

    // ---- Prologue: load Q tile (tf32, unscaled — SCALE applied post-MMA) ----
    for (int i = tid; i < 1024; i += NTHR) {
        int r = i >> 4, c = (i & 15) * 4;
        const float* qp = qkv + (((size_t)b * S_LEN + (t0 + r)) * 3 + 0) * (NH * HD) + h * HD + c;
        sts_tf4(&Qs[r * QS + c], *(const float4*)qp);
    }

    float o[8][4];
    #pragma unroll
    for (int j = 0; j < 8; j++)
        #pragma unroll
        for (int c = 0; c < 4; c++) o[j][c] = 0.f;
    float run_lo = 0.f, run_hi = 0.f;

    const int tg_lo = t0 + m0 + gp;
    const int tg_hi = tg_lo + 8;

    // ---- Key tiles from diagonal down to 0 (suffix-sum order) ----
    for (int kt = tt; kt >= 0; --kt) {
        __syncthreads();   // B1: all warps done reading prev K/V
        const int s0 = kt * 64;

        for (int i = tid; i < 1024; i += NTHR) {
            int r = i >> 4, c = (i & 15) * 4;
            const float* kp = qkv + (((size_t)b * S_LEN + (s0 + r)) * 3 + 1) * (NH * HD) + h * HD + c;
            float4 kv = *(const float4*)kp;
            float4 vv = *(const float4*)(kp + NH * HD);
            sts_tf4(&Ks[r * KS + c], kv);
            sts_tf4(&Vs[r * VS + c], vv);
        }
        __syncthreads();   // B2: K/V ready

        // ---- QK^T: warp computes its 16 rows x all 64 keys ----
        float d[8][4];
        #pragma unroll
        for (int j = 0; j < 8; j++)
            #pragma unroll
            for (int c = 0; c < 4; c++) d[j][c] = 0.f;

        #pragma unroll
        for (int ks = 0; ks < 8; ks++) {
            const int kc = ks * 8;
            uint32_t a0 = __float_as_uint(Qs[(m0 + gp)     * QS + kc + qd]);
            uint32_t a1 = __float_as_uint(Qs[(m0 + gp + 8) * QS + kc + qd]);
            uint32_t a2 = __float_as_uint(Qs[(m0 + gp)     * QS + kc + qd + 4]);
            uint32_t a3 = __float_as_uint(Qs[(m0 + gp + 8) * QS + kc + qd + 4]);
            #pragma unroll
            for (int j = 0; j < 8; j++) {
                uint32_t b0 = __float_as_uint(Ks[(j * 8 + gp) * KS + kc + qd]);
                uint32_t b1 = __float_as_uint(Ks[(j * 8 + gp) * KS + kc + qd + 4]);
                mma_tf32(d[j][0], d[j][1], d[j][2], d[j][3], a0, a1, a2, a3, b0, b1);
            }
        }

        // ---- Stick-breaking scan in registers (j descending = suffix order) ----
        float g_lo = 0.f, g_hi = 0.f;
        #pragma unroll
        for (int j = 7; j >= 0; --j) {
            const int sg = s0 + j * 8 + 2 * qd;
            const float x00 = d[j][0] * SCALE, x01 = d[j][1] * SCALE;
            const float x10 = d[j][2] * SCALE, x11 = d[j][3] * SCALE;
            const bool m00 = sg     < tg_lo, m01 = sg + 1 < tg_lo;
            const bool m10 = sg     < tg_hi, m11 = sg + 1 < tg_hi;
            const float p00 = m00 ? softplus_f(x00) : 0.f;
            const float p01 = m01 ? softplus_f(x01) : 0.f;
            const float p10 = m10 ? softplus_f(x10) : 0.f;
            const float p11 = m11 ? softplus_f(x11) : 0.f;
            const float bs_lo = p00 + p01;
            const float bs_hi = p10 + p11;

            // width-4 suffix-inclusive scan over the quad
            float i_lo = bs_lo, i_hi = bs_hi, u;
            u = __shfl_down_sync(0xffffffffu, i_lo, 1, 4); if (qd < 3) i_lo += u;
            u = __shfl_down_sync(0xffffffffu, i_hi, 1, 4); if (qd < 3) i_hi += u;
            u = __shfl_down_sync(0xffffffffu, i_lo, 2, 4); if (qd < 2) i_lo += u;
            u = __shfl_down_sync(0xffffffffu, i_hi, 2, 4); if (qd < 2) i_hi += u;
            const float T_lo = __shfl_sync(0xffffffffu, i_lo, 0, 4);
            const float T_hi = __shfl_sync(0xffffffffu, i_hi, 0, 4);

            const float e_lo = g_lo + run_lo + (i_lo - bs_lo);
            const float e_hi = g_hi + run_hi + (i_hi - bs_hi);
            const float a00 = m00 ? __expf(x00 - p00 - e_lo - p01) : 0.f;
            const float a01 = m01 ? __expf(x01 - p01 - e_lo)       : 0.f;
            const float a10 = m10 ? __expf(x10 - p10 - e_hi - p11) : 0.f;
            const float a11 = m11 ? __expf(x11 - p11 - e_hi)       : 0.f;

            *(float2*)&At[(m0 + gp)     * AS + j * 8 + 2 * qd] =
                make_float2(__uint_as_float(f2tf(a00)), __uint_as_float(f2tf(a01)));
            *(float2*)&At[(m0 + gp + 8) * AS + j * 8 + 2 * qd] =
                make_float2(__uint_as_float(f2tf(a10)), __uint_as_float(f2tf(a11)));

            g_lo += T_lo;
            g_hi += T_hi;
        }
        run_lo += g_lo;
        run_hi += g_hi;
        __syncwarp();   // At rows are per-warp private: warp-scope ordering suffices

        // ---- A.V: O[rows][64] += att[rows][s] * V[s][64] ----
        #pragma unroll
        for (int ks = 0; ks < 8; ks++) {
            const int kc = ks * 8;
            uint32_t a0 = __float_as_uint(At[(m0 + gp)     * AS + kc + qd]);
            uint32_t a1 = __float_as_uint(At[(m0 + gp + 8) * AS + kc + qd]);
            uint32_t a2 = __float_as_uint(At[(m0 + gp)     * AS + kc + qd + 4]);
            uint32_t a3 = __float_as_uint(At[(m0 + gp + 8) * AS + kc + qd + 4]);
            #pragma unroll
            for (int j = 0; j < 8; j++) {
                uint32_t b0 = __float_as_uint(Vs[(kc + qd)     * VS + j * 8 + gp]);
                uint32_t b1 = __float_as_uint(Vs[(kc + qd + 4) * VS + j * 8 + gp]);
                mma_tf32(o[j][0], o[j][1], o[j][2], o[j][3], a0, a1, a2, a3, b0, b1);
            }
        }
    }

    // ---- Epilogue: out = O + rem * v (v at full fp32 precision) ----
    const float rem_lo = __expf(-run_lo);
    const float rem_hi = __expf(-run_hi);
    const int ra = tg_lo;
    const int rb = tg_hi;
    #pragma unroll
    for (int j = 0; j < 8; j++) {
        const int n0 = j * 8 + 2 * qd;
        const float* vpa = qkv + (((size_t)b * S_LEN + ra) * 3 + 2) * (NH * HD) + h * HD + n0;
        const float* vpb = qkv + (((size_t)b * S_LEN + rb) * 3 + 2) * (NH * HD) + h * HD + n0;
        float2 va = *(const float2*)vpa;
        float2 vb = *(const float2*)vpb;
        float2 oa = make_float2(o[j][0] + rem_lo * va.x, o[j][1] + rem_lo * va.y);
        float2 ob = make_float2(o[j][2] + rem_hi * vb.x, o[j][3] + rem_hi * vb.y);
        *(float2*)(out + (((size_t)b * S_LEN + ra) * NH + h) * HD + n0) = oa;
        *(float2*)(out + (((size_t)b * S_LEN + rb) * NH + h) * HD + n0) = ob;
    }
}

extern "C" void kernel_launch(void* const* d_in, const int* in_sizes, int n_in,
                              void* d_out, int out_size)
{
    const float* qkv = (const float*)d_in[0];
    float* out = (float*)d_out;

    cudaFuncSetAttribute(sb_attn_kernel,
                         cudaFuncAttributeMaxDynamicSharedMemorySize,
                         SMEM_FLOATS * sizeof(float));

    dim3 grid(S_LEN / 64, NH, 2);   // (32, 16, 2)
    sb_attn_kernel<<<grid, NTHR, SMEM_FLOATS * sizeof(float)>>>(qkv, out);
}

// round 7
// speedup vs baseline: 2.6759x; 1.4062x over previous
#include <cuda_runtime.h>
#include <cstdint>

#define S_LEN 2048
#define NH    16
#define HD    64
#define NTHR  128
#define SCALE 0.1875f   // 1.5 / sqrt(64)

#define QS 68
#define KS 68
#define VS 72
#define AS 68
// Qs[64*68] | Ks[64*68] | Vs[64*72] | At[64*68]
#define SMEM_FLOATS (64*QS + 64*KS + 64*VS + 64*AS)

__device__ __forceinline__ uint32_t f2tf(float x) {
    uint32_t r; asm("cvt.rna.tf32.f32 %0, %1;" : "=r"(r) : "f"(x)); return r;
}

__device__ __forceinline__ void mma_tf32(float& d0, float& d1, float& d2, float& d3,
                                         uint32_t a0, uint32_t a1, uint32_t a2, uint32_t a3,
                                         uint32_t b0, uint32_t b1) {
    asm volatile("mma.sync.aligned.m16n8k8.row.col.f32.tf32.tf32.f32 "
                 "{%0,%1,%2,%3}, {%4,%5,%6,%7}, {%8,%9}, {%0,%1,%2,%3};"
                 : "+f"(d0), "+f"(d1), "+f"(d2), "+f"(d3)
                 : "r"(a0), "r"(a1), "r"(a2), "r"(a3), "r"(b0), "r"(b1));
}

__device__ __forceinline__ void sts_tf4(float* dst, float4 v) {
    dst[0] = __uint_as_float(f2tf(v.x));
    dst[1] = __uint_as_float(f2tf(v.y));
    dst[2] = __uint_as_float(f2tf(v.z));
    dst[3] = __uint_as_float(f2tf(v.w));
}

// stable sigmoid pair: sg = sigma(x), om = 1 - sigma(x); masked -> sg=0, om=1
__device__ __forceinline__ void sig_pair(float x, bool mask, float& sg, float& om) {
    const float t = __expf(-fabsf(x));          // MUFU exp
    const float r = __fdividef(1.f, 1.f + t);   // MUFU rcp
    const float tr = t * r;
    const bool pos = x >= 0.f;
    sg = mask ? (pos ? r : tr) : 0.f;
    om = mask ? (pos ? tr : r) : 1.f;
}

__global__ void __launch_bounds__(NTHR, 3)
sb_attn_kernel(const float* __restrict__ qkv, float* __restrict__ out)
{
    extern __shared__ float smem[];
    float* Qs = smem;                 // [64][68] tf32 (unscaled)
    float* Ks = Qs + 64 * QS;         // [64][68] tf32
    float* Vs = Ks + 64 * KS;         // [64][72] tf32
    float* At = Vs + 64 * VS;         // [64][68] att (tf32 bits), per-warp private rows

    const int tt   = (int)gridDim.x - 1 - (int)blockIdx.x;  // heavy tiles first
    const int h    = blockIdx.y;
    const int b    = blockIdx.z;
    const int tid  = threadIdx.x;
    const int warp = tid >> 5;
    const int lane = tid & 31;
    const int gp   = lane >> 2;   // 0..7
    const int qd   = lane & 3;    // 0..3
    const int m0   = warp * 16;   // warp owns rows m0..m0+15, ALL 64 cols
    const int t0   = tt * 64;

    // ---- Prologue: load Q tile (tf32, unscaled — SCALE applied post-MMA) ----
    for (int i = tid; i < 1024; i += NTHR) {
        int r = i >> 4, c = (i & 15) * 4;
        const float* qp = qkv + (((size_t)b * S_LEN + (t0 + r)) * 3 + 0) * (NH * HD) + h * HD + c;
        sts_tf4(&Qs[r * QS + c], *(const float4*)qp);
    }

    float o[8][4];
    #pragma unroll
    for (int j = 0; j < 8; j++)
        #pragma unroll
        for (int c = 0; c < 4; c++) o[j][c] = 0.f;

    // running suffix PRODUCTS of (1 - sigma) from all later keys
    float R_lo = 1.f, R_hi = 1.f;

    const int tg_lo = t0 + m0 + gp;
    const int tg_hi = tg_lo + 8;

    // ---- Key tiles from diagonal down to 0 (suffix order) ----
    for (int kt = tt; kt >= 0; --kt) {
        __syncthreads();   // B1: all warps done reading prev K/V
        const int s0 = kt * 64;

        for (int i = tid; i < 1024; i += NTHR) {
            int r = i >> 4, c = (i & 15) * 4;
            const float* kp = qkv + (((size_t)b * S_LEN + (s0 + r)) * 3 + 1) * (NH * HD) + h * HD + c;
            float4 kv = *(const float4*)kp;
            float4 vv = *(const float4*)(kp + NH * HD);
            sts_tf4(&Ks[r * KS + c], kv);
            sts_tf4(&Vs[r * VS + c], vv);
        }
        __syncthreads();   // B2: K/V ready

        // ---- QK^T: warp computes its 16 rows x all 64 keys ----
        float d[8][4];
        #pragma unroll
        for (int j = 0; j < 8; j++)
            #pragma unroll
            for (int c = 0; c < 4; c++) d[j][c] = 0.f;

        #pragma unroll
        for (int ks = 0; ks < 8; ks++) {
            const int kc = ks * 8;
            uint32_t a0 = __float_as_uint(Qs[(m0 + gp)     * QS + kc + qd]);
            uint32_t a1 = __float_as_uint(Qs[(m0 + gp + 8) * QS + kc + qd]);
            uint32_t a2 = __float_as_uint(Qs[(m0 + gp)     * QS + kc + qd + 4]);
            uint32_t a3 = __float_as_uint(Qs[(m0 + gp + 8) * QS + kc + qd + 4]);
            #pragma unroll
            for (int j = 0; j < 8; j++) {
                uint32_t b0 = __float_as_uint(Ks[(j * 8 + gp) * KS + kc + qd]);
                uint32_t b1 = __float_as_uint(Ks[(j * 8 + gp) * KS + kc + qd + 4]);
                mma_tf32(d[j][0], d[j][1], d[j][2], d[j][3], a0, a1, a2, a3, b0, b1);
            }
        }

        // ---- Multiplicative stick-breaking scan (j descending = suffix order) ----
        #pragma unroll
        for (int j = 7; j >= 0; --j) {
            const int sg0 = s0 + j * 8 + 2 * qd;
            const bool m00 = sg0     < tg_lo, m01 = sg0 + 1 < tg_lo;
            const bool m10 = sg0     < tg_hi, m11 = sg0 + 1 < tg_hi;

            float sg00, om00, sg01, om01, sg10, om10, sg11, om11;
            sig_pair(d[j][0] * SCALE, m00, sg00, om00);
            sig_pair(d[j][1] * SCALE, m01, sg01, om01);
            sig_pair(d[j][2] * SCALE, m10, sg10, om10);
            sig_pair(d[j][3] * SCALE, m11, sg11, om11);

            const float bs_lo = om00 * om01;
            const float bs_hi = om10 * om11;

            // width-4 suffix-inclusive PRODUCT scan over the quad
            float i_lo = bs_lo, i_hi = bs_hi, u;
            u = __shfl_down_sync(0xffffffffu, i_lo, 1, 4); if (qd < 3) i_lo *= u;
            u = __shfl_down_sync(0xffffffffu, i_hi, 1, 4); if (qd < 3) i_hi *= u;
            u = __shfl_down_sync(0xffffffffu, i_lo, 2, 4); if (qd < 2) i_lo *= u;
            u = __shfl_down_sync(0xffffffffu, i_hi, 2, 4); if (qd < 2) i_hi *= u;

            // exclusive suffix (pairs strictly after this quad lane) + quad total
            float ex_lo = __shfl_down_sync(0xffffffffu, i_lo, 1, 4);
            float ex_hi = __shfl_down_sync(0xffffffffu, i_hi, 1, 4);
            if (qd == 3) { ex_lo = 1.f; ex_hi = 1.f; }
            const float T_lo = __shfl_sync(0xffffffffu, i_lo, 0, 4);
            const float T_hi = __shfl_sync(0xffffffffu, i_hi, 0, 4);

            const float E_lo = ex_lo * R_lo;
            const float E_hi = ex_hi * R_hi;
            const float a00 = sg00 * om01 * E_lo;
            const float a01 = sg01 * E_lo;
            const float a10 = sg10 * om11 * E_hi;
            const float a11 = sg11 * E_hi;

            *(float2*)&At[(m0 + gp)     * AS + j * 8 + 2 * qd] =
                make_float2(__uint_as_float(f2tf(a00)), __uint_as_float(f2tf(a01)));
            *(float2*)&At[(m0 + gp + 8) * AS + j * 8 + 2 * qd] =
                make_float2(__uint_as_float(f2tf(a10)), __uint_as_float(f2tf(a11)));

            R_lo *= T_lo;
            R_hi *= T_hi;
        }
        __syncwarp();   // At rows are per-warp private: warp-scope ordering suffices

        // ---- A.V: O[rows][64] += att[rows][s] * V[s][64] ----
        #pragma unroll
        for (int ks = 0; ks < 8; ks++) {
            const int kc = ks * 8;
            uint32_t a0 = __float_as_uint(At[(m0 + gp)     * AS + kc + qd]);
            uint32_t a1 = __float_as_uint(At[(m0 + gp + 8) * AS + kc + qd]);
            uint32_t a2 = __float_as_uint(At[(m0 + gp)     * AS + kc + qd + 4]);
            uint32_t a3 = __float_as_uint(At[(m0 + gp + 8) * AS + kc + qd + 4]);
            #pragma unroll
            for (int j = 0; j < 8; j++) {
                uint32_t b0 = __float_as_uint(Vs[(kc + qd)     * VS + j * 8 + gp]);
                uint32_t b1 = __float_as_uint(Vs[(kc + qd + 4) * VS + j * 8 + gp]);
                mma_tf32(o[j][0], o[j][1], o[j][2], o[j][3], a0, a1, a2, a3, b0, b1);
            }
        }
    }

    // ---- Epilogue: out = O + rem * v ; rem is the final running product ----
    const float rem_lo = R_lo;
    const float rem_hi = R_hi;
    const int ra = tg_lo;
    const int rb = tg_hi;
    #pragma unroll
    for (int j = 0; j < 8; j++) {
        const int n0 = j * 8 + 2 * qd;
        const float* vpa = qkv + (((size_t)b * S_LEN + ra) * 3 + 2) * (NH * HD) + h * HD + n0;
        const float* vpb = qkv + (((size_t)b * S_LEN + rb) * 3 + 2) * (NH * HD) + h * HD + n0;
        float2 va = *(const float2*)vpa;
        float2 vb = *(const float2*)vpb;
        float2 oa = make_float2(o[j][0] + rem_lo * va.x, o[j][1] + rem_lo * va.y);
        float2 ob = make_float2(o[j][2] + rem_hi * vb.x, o[j][3] + rem_hi * vb.y);
        *(float2*)(out + (((size_t)b * S_LEN + ra) * NH + h) * HD + n0) = oa;
        *(float2*)(out + (((size_t)b * S_LEN + rb) * NH + h) * HD + n0) = ob;
    }
}

extern "C" void kernel_launch(void* const* d_in, const int* in_sizes, int n_in,
                              void* d_out, int out_size)
{
    const float* qkv = (const float*)d_in[0];
    float* out = (float*)d_out;

    cudaFuncSetAttribute(sb_attn_kernel,
                         cudaFuncAttributeMaxDynamicSharedMemorySize,
                         SMEM_FLOATS * sizeof(float));

    dim3 grid(S_LEN / 64, NH, 2);   // (32, 16, 2)
    sb_attn_kernel<<<grid, NTHR, SMEM_FLOATS * sizeof(float)>>>(qkv, out);
}

// round 8
// speedup vs baseline: 3.0798x; 1.1509x over previous
#include <cuda_runtime.h>
#include <cstdint>

#define S_LEN 2048
#define NH    16
#define HD    64
#define NTHR  128
#define SCALE 0.1875f   // 1.5 / sqrt(64)

#define KS 68
#define VS 72
#define AS 68
// K[2][64*68] | Vs[64*72] | At[64*68]   (Q lives in registers)
#define SMEM_FLOATS (2*64*KS + 64*VS + 64*AS)

__device__ __forceinline__ uint32_t f2tf(float x) {
    uint32_t r; asm("cvt.rna.tf32.f32 %0, %1;" : "=r"(r) : "f"(x)); return r;
}

__device__ __forceinline__ void cp16(uint32_t saddr, const float* g) {
    asm volatile("cp.async.cg.shared.global [%0], [%1], 16;" :: "r"(saddr), "l"(g) : "memory");
}

__device__ __forceinline__ void mma_tf32(float& d0, float& d1, float& d2, float& d3,
                                         uint32_t a0, uint32_t a1, uint32_t a2, uint32_t a3,
                                         uint32_t b0, uint32_t b1) {
    asm volatile("mma.sync.aligned.m16n8k8.row.col.f32.tf32.tf32.f32 "
                 "{%0,%1,%2,%3}, {%4,%5,%6,%7}, {%8,%9}, {%0,%1,%2,%3};"
                 : "+f"(d0), "+f"(d1), "+f"(d2), "+f"(d3)
                 : "r"(a0), "r"(a1), "r"(a2), "r"(a3), "r"(b0), "r"(b1));
}

// stable sigmoid pair: sg = sigma(x), om = 1 - sigma(x); masked -> sg=0, om=1
__device__ __forceinline__ void sig_pair(float x, bool mask, float& sg, float& om) {
    const float t = __expf(-fabsf(x));          // MUFU exp
    const float r = __fdividef(1.f, 1.f + t);   // MUFU rcp
    const float tr = t * r;
    const bool pos = x >= 0.f;
    sg = mask ? (pos ? r : tr) : 0.f;
    om = mask ? (pos ? tr : r) : 1.f;
}

__global__ void __launch_bounds__(NTHR, 3)
sb_attn_kernel(const float* __restrict__ qkv, float* __restrict__ out)
{
    extern __shared__ float smem[];
    float* Ksb = smem;                 // [2][64][68] raw f32 (tf32 via truncation)
    float* Vs  = Ksb + 2 * 64 * KS;    // [64][72] raw f32
    float* At  = Vs + 64 * VS;         // [64][68] att (raw f32), per-warp private rows

    const int tt   = (int)gridDim.x - 1 - (int)blockIdx.x;  // heavy tiles first
    const int h    = blockIdx.y;
    const int b    = blockIdx.z;
    const int tid  = threadIdx.x;
    const int warp = tid >> 5;
    const int lane = tid & 31;
    const int gp   = lane >> 2;   // 0..7
    const int qd   = lane & 3;    // 0..3
    const int m0   = warp * 16;   // warp owns rows m0..m0+15, ALL 64 cols
    const int t0   = tt * 64;

    const int tg_lo = t0 + m0 + gp;
    const int tg_hi = tg_lo + 8;

    const uint32_t s_k = (uint32_t)__cvta_generic_to_shared(Ksb);
    const uint32_t s_v = (uint32_t)__cvta_generic_to_shared(Vs);

    // per-thread staging coords: c fixed, rows r0 + 8p
    const int r0 = tid >> 4;
    const int c0 = (tid & 15) * 4;

    // ---- Q fragments in registers: RNA tf32, pre-scaled (loaded once) ----
    uint32_t qa[8][4];
    {
        const float* qlo = qkv + (((size_t)b * S_LEN + tg_lo) * 3 + 0) * (NH * HD) + h * HD;
        const float* qhi = qkv + (((size_t)b * S_LEN + tg_hi) * 3 + 0) * (NH * HD) + h * HD;
        #pragma unroll
        for (int ks = 0; ks < 8; ks++) {
            qa[ks][0] = f2tf(SCALE * qlo[ks * 8 + qd]);
            qa[ks][1] = f2tf(SCALE * qhi[ks * 8 + qd]);
            qa[ks][2] = f2tf(SCALE * qlo[ks * 8 + qd + 4]);
            qa[ks][3] = f2tf(SCALE * qhi[ks * 8 + qd + 4]);
        }
    }

    // ---- Prologue: async-load diagonal K tile ----
    {
        const uint32_t kb = s_k + (uint32_t)(tt & 1) * (64 * KS * 4);
        const float* kg = qkv + (((size_t)b * S_LEN + (t0 + r0)) * 3 + 1) * (NH * HD) + h * HD + c0;
        #pragma unroll
        for (int p = 0; p < 8; p++)
            cp16(kb + (uint32_t)((r0 + 8 * p) * KS + c0) * 4u, kg + (size_t)p * 8 * 3 * NH * HD);
        asm volatile("cp.async.commit_group;" ::: "memory");
    }

    float o[8][4];
    #pragma unroll
    for (int j = 0; j < 8; j++)
        #pragma unroll
        for (int c = 0; c < 4; c++) o[j][c] = 0.f;
    float R_lo = 1.f, R_hi = 1.f;

    // ---- Key tiles from diagonal down to 0 (suffix order) ----
    for (int kt = tt; kt >= 0; --kt) {
        asm volatile("cp.async.wait_group 0;" ::: "memory");   // K_kt arrived (mine)
        __syncthreads();   // B1: K_kt visible to all; AV(prev) done -> Vs free

        const int s0 = kt * 64;

        // issue V_kt (this tile) -> Vs
        {
            const float* vg = qkv + (((size_t)b * S_LEN + (s0 + r0)) * 3 + 2) * (NH * HD) + h * HD + c0;
            #pragma unroll
            for (int p = 0; p < 8; p++)
                cp16(s_v + (uint32_t)((r0 + 8 * p) * VS + c0) * 4u, vg + (size_t)p * 8 * 3 * NH * HD);
            asm volatile("cp.async.commit_group;" ::: "memory");
        }
        // prefetch K_{kt-1} -> other K buffer
        if (kt > 0) {
            const int s0n = (kt - 1) * 64;
            const uint32_t kb = s_k + (uint32_t)((kt - 1) & 1) * (64 * KS * 4);
            const float* kg = qkv + (((size_t)b * S_LEN + (s0n + r0)) * 3 + 1) * (NH * HD) + h * HD + c0;
            #pragma unroll
            for (int p = 0; p < 8; p++)
                cp16(kb + (uint32_t)((r0 + 8 * p) * KS + c0) * 4u, kg + (size_t)p * 8 * 3 * NH * HD);
            asm volatile("cp.async.commit_group;" ::: "memory");
        }

        const float* Kb = Ksb + (kt & 1) * (64 * KS);

        // ---- QK^T: warp computes its 16 rows x all 64 keys ----
        float d[8][4];
        #pragma unroll
        for (int j = 0; j < 8; j++)
            #pragma unroll
            for (int c = 0; c < 4; c++) d[j][c] = 0.f;

        #pragma unroll
        for (int ks = 0; ks < 8; ks++) {
            const int kc = ks * 8;
            #pragma unroll
            for (int j = 0; j < 8; j++) {
                uint32_t b0 = __float_as_uint(Kb[(j * 8 + gp) * KS + kc + qd]);
                uint32_t b1 = __float_as_uint(Kb[(j * 8 + gp) * KS + kc + qd + 4]);
                mma_tf32(d[j][0], d[j][1], d[j][2], d[j][3],
                         qa[ks][0], qa[ks][1], qa[ks][2], qa[ks][3], b0, b1);
            }
        }

        // ---- Multiplicative stick-breaking scan (j descending = suffix order) ----
        #pragma unroll
        for (int j = 7; j >= 0; --j) {
            const int sg0 = s0 + j * 8 + 2 * qd;
            const bool m00 = sg0     < tg_lo, m01 = sg0 + 1 < tg_lo;
            const bool m10 = sg0     < tg_hi, m11 = sg0 + 1 < tg_hi;

            float sg00, om00, sg01, om01, sg10, om10, sg11, om11;
            sig_pair(d[j][0], m00, sg00, om00);
            sig_pair(d[j][1], m01, sg01, om01);
            sig_pair(d[j][2], m10, sg10, om10);
            sig_pair(d[j][3], m11, sg11, om11);

            const float bs_lo = om00 * om01;
            const float bs_hi = om10 * om11;

            // width-4 suffix-inclusive PRODUCT scan over the quad
            float i_lo = bs_lo, i_hi = bs_hi, u;
            u = __shfl_down_sync(0xffffffffu, i_lo, 1, 4); if (qd < 3) i_lo *= u;
            u = __shfl_down_sync(0xffffffffu, i_hi, 1, 4); if (qd < 3) i_hi *= u;
            u = __shfl_down_sync(0xffffffffu, i_lo, 2, 4); if (qd < 2) i_lo *= u;
            u = __shfl_down_sync(0xffffffffu, i_hi, 2, 4); if (qd < 2) i_hi *= u;

            float ex_lo = __shfl_down_sync(0xffffffffu, i_lo, 1, 4);
            float ex_hi = __shfl_down_sync(0xffffffffu, i_hi, 1, 4);
            if (qd == 3) { ex_lo = 1.f; ex_hi = 1.f; }
            const float T_lo = __shfl_sync(0xffffffffu, i_lo, 0, 4);
            const float T_hi = __shfl_sync(0xffffffffu, i_hi, 0, 4);

            const float E_lo = ex_lo * R_lo;
            const float E_hi = ex_hi * R_hi;

            *(float2*)&At[(m0 + gp)     * AS + j * 8 + 2 * qd] =
                make_float2(sg00 * om01 * E_lo, sg01 * E_lo);
            *(float2*)&At[(m0 + gp + 8) * AS + j * 8 + 2 * qd] =
                make_float2(sg10 * om11 * E_hi, sg11 * E_hi);

            R_lo *= T_lo;
            R_hi *= T_hi;
        }

        // V_kt must have landed (K prefetch may remain in flight)
        if (kt > 0) { asm volatile("cp.async.wait_group 1;" ::: "memory"); }
        else        { asm volatile("cp.async.wait_group 0;" ::: "memory"); }
        __syncthreads();   // B2: V visible to all (also covers At per-warp ordering)

        // ---- A.V: O[rows][64] += att[rows][s] * V[s][64] ----
        #pragma unroll
        for (int ks = 0; ks < 8; ks++) {
            const int kc = ks * 8;
            uint32_t a0 = __float_as_uint(At[(m0 + gp)     * AS + kc + qd]);
            uint32_t a1 = __float_as_uint(At[(m0 + gp + 8) * AS + kc + qd]);
            uint32_t a2 = __float_as_uint(At[(m0 + gp)     * AS + kc + qd + 4]);
            uint32_t a3 = __float_as_uint(At[(m0 + gp + 8) * AS + kc + qd + 4]);
            #pragma unroll
            for (int j = 0; j < 8; j++) {
                uint32_t b0 = __float_as_uint(Vs[(kc + qd)     * VS + j * 8 + gp]);
                uint32_t b1 = __float_as_uint(Vs[(kc + qd + 4) * VS + j * 8 + gp]);
                mma_tf32(o[j][0], o[j][1], o[j][2], o[j][3], a0, a1, a2, a3, b0, b1);
            }
        }
    }

    // ---- Epilogue: out = O + rem * v ; rem is the final running product ----
    const float rem_lo = R_lo;
    const float rem_hi = R_hi;
    #pragma unroll
    for (int j = 0; j < 8; j++) {
        const int n0 = j * 8 + 2 * qd;
        const float* vpa = qkv + (((size_t)b * S_LEN + tg_lo) * 3 + 2) * (NH * HD) + h * HD + n0;
        const float* vpb = qkv + (((size_t)b * S_LEN + tg_hi) * 3 + 2) * (NH * HD) + h * HD + n0;
        float2 va = *(const float2*)vpa;
        float2 vb = *(const float2*)vpb;
        float2 oa = make_float2(o[j][0] + rem_lo * va.x, o[j][1] + rem_lo * va.y);
        float2 ob = make_float2(o[j][2] + rem_hi * vb.x, o[j][3] + rem_hi * vb.y);
        *(float2*)(out + (((size_t)b * S_LEN + tg_lo) * NH + h) * HD + n0) = oa;
        *(float2*)(out + (((size_t)b * S_LEN + tg_hi) * NH + h) * HD + n0) = ob;
    }
}

extern "C" void kernel_launch(void* const* d_in, const int* in_sizes, int n_in,
                              void* d_out, int out_size)
{
    const float* qkv = (const float*)d_in[0];
    float* out = (float*)d_out;

    cudaFuncSetAttribute(sb_attn_kernel,
                         cudaFuncAttributeMaxDynamicSharedMemorySize,
                         SMEM_FLOATS * sizeof(float));

    dim3 grid(S_LEN / 64, NH, 2);   // (32, 16, 2)
    sb_attn_kernel<<<grid, NTHR, SMEM_FLOATS * sizeof(float)>>>(qkv, out);
}

// round 9
// speedup vs baseline: 3.2997x; 1.0714x over previous
#include <cuda_runtime.h>
#include <cstdint>

#define S_LEN 2048
#define NH    16
#define HD    64
#define NTHR  128
#define SCALE 0.1875f   // 1.5 / sqrt(64)

#define KS 68
#define VS 72
#define AS 68
// K[2][64*68] | Vs[64*72] | At[64*68]   (Q lives in registers)
#define SMEM_FLOATS (2*64*KS + 64*VS + 64*AS)

__device__ __forceinline__ uint32_t f2tf(float x) {
    uint32_t r; asm("cvt.rna.tf32.f32 %0, %1;" : "=r"(r) : "f"(x)); return r;
}

__device__ __forceinline__ void cp16(uint32_t saddr, const float* g) {
    asm volatile("cp.async.cg.shared.global [%0], [%1], 16;" :: "r"(saddr), "l"(g) : "memory");
}

__device__ __forceinline__ void ldsm_x4(uint32_t& r0, uint32_t& r1, uint32_t& r2, uint32_t& r3,
                                        uint32_t saddr) {
    asm volatile("ldmatrix.sync.aligned.m8n8.x4.shared.b16 {%0,%1,%2,%3}, [%4];"
                 : "=r"(r0), "=r"(r1), "=r"(r2), "=r"(r3) : "r"(saddr));
}

__device__ __forceinline__ void mma_tf32(float& d0, float& d1, float& d2, float& d3,
                                         uint32_t a0, uint32_t a1, uint32_t a2, uint32_t a3,
                                         uint32_t b0, uint32_t b1) {
    asm volatile("mma.sync.aligned.m16n8k8.row.col.f32.tf32.tf32.f32 "
                 "{%0,%1,%2,%3}, {%4,%5,%6,%7}, {%8,%9}, {%0,%1,%2,%3};"
                 : "+f"(d0), "+f"(d1), "+f"(d2), "+f"(d3)
                 : "r"(a0), "r"(a1), "r"(a2), "r"(a3), "r"(b0), "r"(b1));
}

// stable sigmoid pair: sg = sigma(x), om = 1 - sigma(x); masked -> sg=0, om=1
__device__ __forceinline__ void sig_pair(float x, bool mask, float& sg, float& om) {
    const float t = __expf(-fabsf(x));          // MUFU exp
    const float r = __fdividef(1.f, 1.f + t);   // MUFU rcp
    const float tr = t * r;
    const bool pos = x >= 0.f;
    sg = mask ? (pos ? r : tr) : 0.f;
    om = mask ? (pos ? tr : r) : 1.f;
}

__global__ void __launch_bounds__(NTHR, 3)
sb_attn_kernel(const float* __restrict__ qkv, float* __restrict__ out)
{
    extern __shared__ float smem[];
    float* Ksb = smem;                 // [2][64][68] raw f32 (tf32 via truncation)
    float* Vs  = Ksb + 2 * 64 * KS;    // [64][72] raw f32
    float* At  = Vs + 64 * VS;         // [64][68] att (RNA tf32 bits), per-warp private rows

    const int tt   = (int)gridDim.x - 1 - (int)blockIdx.x;  // heavy tiles first
    const int h    = blockIdx.y;
    const int b    = blockIdx.z;
    const int tid  = threadIdx.x;
    const int warp = tid >> 5;
    const int lane = tid & 31;
    const int gp   = lane >> 2;   // 0..7
    const int qd   = lane & 3;    // 0..3
    const int m0   = warp * 16;   // warp owns rows m0..m0+15, ALL 64 cols
    const int t0   = tt * 64;

    const int tg_lo = t0 + m0 + gp;
    const int tg_hi = tg_lo + 8;

    const uint32_t s_k  = (uint32_t)__cvta_generic_to_shared(Ksb);
    const uint32_t s_v  = (uint32_t)__cvta_generic_to_shared(Vs);
    const uint32_t s_at = (uint32_t)__cvta_generic_to_shared(At);

    // ldmatrix per-thread geometry: mat = which 8x8 matrix, mrow = row within it
    const int mat  = lane >> 3;   // 0..3
    const int mrow = lane & 7;
    // K: mats = (j,cols0-3),(j,cols4-7),(j+1,cols0-3),(j+1,cols4-7)
    const uint32_t k_lm_off = 4u * ((uint32_t)(((mat >> 1) * 8 + mrow) * KS) + (uint32_t)((mat & 1) * 4));
    // At: mats = (rows lo,cols0-3),(rows hi,cols0-3),(rows lo,+4),(rows hi,+4)
    const uint32_t at_lm_base = s_at + 4u * ((uint32_t)((m0 + (mat & 1) * 8 + mrow) * AS) + (uint32_t)((mat >> 1) * 4));

    // per-thread staging coords: c fixed, rows r0 + 8p
    const int r0 = tid >> 4;
    const int c0 = (tid & 15) * 4;

    // ---- Q fragments in registers: RNA tf32, pre-scaled (loaded once) ----
    uint32_t qa[8][4];
    {
        const float* qlo = qkv + (((size_t)b * S_LEN + tg_lo) * 3 + 0) * (NH * HD) + h * HD;
        const float* qhi = qkv + (((size_t)b * S_LEN + tg_hi) * 3 + 0) * (NH * HD) + h * HD;
        #pragma unroll
        for (int ks = 0; ks < 8; ks++) {
            qa[ks][0] = f2tf(SCALE * qlo[ks * 8 + qd]);
            qa[ks][1] = f2tf(SCALE * qhi[ks * 8 + qd]);
            qa[ks][2] = f2tf(SCALE * qlo[ks * 8 + qd + 4]);
            qa[ks][3] = f2tf(SCALE * qhi[ks * 8 + qd + 4]);
        }
    }

    // ---- Prologue: async-load diagonal K tile ----
    {
        const uint32_t kb = s_k + (uint32_t)(tt & 1) * (64 * KS * 4);
        const float* kg = qkv + (((size_t)b * S_LEN + (t0 + r0)) * 3 + 1) * (NH * HD) + h * HD + c0;
        #pragma unroll
        for (int p = 0; p < 8; p++)
            cp16(kb + (uint32_t)((r0 + 8 * p) * KS + c0) * 4u, kg + (size_t)p * 8 * 3 * NH * HD);
        asm volatile("cp.async.commit_group;" ::: "memory");
    }

    float o[8][4];
    #pragma unroll
    for (int j = 0; j < 8; j++)
        #pragma unroll
        for (int c = 0; c < 4; c++) o[j][c] = 0.f;
    float R_lo = 1.f, R_hi = 1.f;

    // ---- Key tiles from diagonal down to 0 (suffix order) ----
    for (int kt = tt; kt >= 0; --kt) {
        asm volatile("cp.async.wait_group 0;" ::: "memory");   // K_kt arrived
        __syncthreads();   // B1: K_kt visible to all; AV(prev) done -> Vs free

        const int s0 = kt * 64;

        // issue V_kt (this tile) -> Vs
        {
            const float* vg = qkv + (((size_t)b * S_LEN + (s0 + r0)) * 3 + 2) * (NH * HD) + h * HD + c0;
            #pragma unroll
            for (int p = 0; p < 8; p++)
                cp16(s_v + (uint32_t)((r0 + 8 * p) * VS + c0) * 4u, vg + (size_t)p * 8 * 3 * NH * HD);
            asm volatile("cp.async.commit_group;" ::: "memory");
        }
        // prefetch K_{kt-1} -> other K buffer
        if (kt > 0) {
            const int s0n = (kt - 1) * 64;
            const uint32_t kb = s_k + (uint32_t)((kt - 1) & 1) * (64 * KS * 4);
            const float* kg = qkv + (((size_t)b * S_LEN + (s0n + r0)) * 3 + 1) * (NH * HD) + h * HD + c0;
            #pragma unroll
            for (int p = 0; p < 8; p++)
                cp16(kb + (uint32_t)((r0 + 8 * p) * KS + c0) * 4u, kg + (size_t)p * 8 * 3 * NH * HD);
            asm volatile("cp.async.commit_group;" ::: "memory");
        }

        const uint32_t k_lm = s_k + (uint32_t)(kt & 1) * (64 * KS * 4) + k_lm_off;

        // ---- QK^T: ldmatrix.x4 loads B-frags for 2 j-blocks per instruction ----
        float d[8][4];
        #pragma unroll
        for (int j = 0; j < 8; j++)
            #pragma unroll
            for (int c = 0; c < 4; c++) d[j][c] = 0.f;

        #pragma unroll
        for (int ks = 0; ks < 8; ks++) {
            #pragma unroll
            for (int jp = 0; jp < 4; jp++) {
                uint32_t b0a, b1a, b0b, b1b;
                ldsm_x4(b0a, b1a, b0b, b1b,
                        k_lm + 4u * (uint32_t)(jp * 16 * KS + 8 * ks));
                mma_tf32(d[2*jp][0], d[2*jp][1], d[2*jp][2], d[2*jp][3],
                         qa[ks][0], qa[ks][1], qa[ks][2], qa[ks][3], b0a, b1a);
                mma_tf32(d[2*jp+1][0], d[2*jp+1][1], d[2*jp+1][2], d[2*jp+1][3],
                         qa[ks][0], qa[ks][1], qa[ks][2], qa[ks][3], b0b, b1b);
            }
        }

        // ---- Multiplicative stick-breaking scan (j descending = suffix order) ----
        #pragma unroll
        for (int j = 7; j >= 0; --j) {
            const int sg0 = s0 + j * 8 + 2 * qd;
            const bool m00 = sg0     < tg_lo, m01 = sg0 + 1 < tg_lo;
            const bool m10 = sg0     < tg_hi, m11 = sg0 + 1 < tg_hi;

            float sg00, om00, sg01, om01, sg10, om10, sg11, om11;
            sig_pair(d[j][0], m00, sg00, om00);
            sig_pair(d[j][1], m01, sg01, om01);
            sig_pair(d[j][2], m10, sg10, om10);
            sig_pair(d[j][3], m11, sg11, om11);

            const float bs_lo = om00 * om01;
            const float bs_hi = om10 * om11;

            // width-4 suffix-inclusive PRODUCT scan over the quad
            float i_lo = bs_lo, i_hi = bs_hi, u;
            u = __shfl_down_sync(0xffffffffu, i_lo, 1, 4); if (qd < 3) i_lo *= u;
            u = __shfl_down_sync(0xffffffffu, i_hi, 1, 4); if (qd < 3) i_hi *= u;
            u = __shfl_down_sync(0xffffffffu, i_lo, 2, 4); if (qd < 2) i_lo *= u;
            u = __shfl_down_sync(0xffffffffu, i_hi, 2, 4); if (qd < 2) i_hi *= u;

            float ex_lo = __shfl_down_sync(0xffffffffu, i_lo, 1, 4);
            float ex_hi = __shfl_down_sync(0xffffffffu, i_hi, 1, 4);
            if (qd == 3) { ex_lo = 1.f; ex_hi = 1.f; }
            const float T_lo = __shfl_sync(0xffffffffu, i_lo, 0, 4);
            const float T_hi = __shfl_sync(0xffffffffu, i_hi, 0, 4);

            const float E_lo = ex_lo * R_lo;
            const float E_hi = ex_hi * R_hi;

            // att staged with RNA tf32 rounding (kills RZ positive bias)
            *(float2*)&At[(m0 + gp)     * AS + j * 8 + 2 * qd] =
                make_float2(__uint_as_float(f2tf(sg00 * om01 * E_lo)),
                            __uint_as_float(f2tf(sg01 * E_lo)));
            *(float2*)&At[(m0 + gp + 8) * AS + j * 8 + 2 * qd] =
                make_float2(__uint_as_float(f2tf(sg10 * om11 * E_hi)),
                            __uint_as_float(f2tf(sg11 * E_hi)));

            R_lo *= T_lo;
            R_hi *= T_hi;
        }

        // V_kt must have landed (K prefetch may remain in flight)
        if (kt > 0) { asm volatile("cp.async.wait_group 1;" ::: "memory"); }
        else        { asm volatile("cp.async.wait_group 0;" ::: "memory"); }
        __syncthreads();   // B2: V visible to all (also orders At across the ldmatrix path)

        // ---- A.V: A-frags via ldmatrix.x4 (one per ks); V scalar ----
        #pragma unroll
        for (int ks = 0; ks < 8; ks++) {
            const int kc = ks * 8;
            uint32_t a0, a1, a2, a3;
            ldsm_x4(a0, a1, a2, a3, at_lm_base + 32u * (uint32_t)ks);
            #pragma unroll
            for (int j = 0; j < 8; j++) {
                uint32_t b0 = __float_as_uint(Vs[(kc + qd)     * VS + j * 8 + gp]);
                uint32_t b1 = __float_as_uint(Vs[(kc + qd + 4) * VS + j * 8 + gp]);
                mma_tf32(o[j][0], o[j][1], o[j][2], o[j][3], a0, a1, a2, a3, b0, b1);
            }
        }
    }

    // ---- Epilogue: out = O + rem * v ; rem is the final running product ----
    const float rem_lo = R_lo;
    const float rem_hi = R_hi;
    #pragma unroll
    for (int j = 0; j < 8; j++) {
        const int n0 = j * 8 + 2 * qd;
        const float* vpa = qkv + (((size_t)b * S_LEN + tg_lo) * 3 + 2) * (NH * HD) + h * HD + n0;
        const float* vpb = qkv + (((size_t)b * S_LEN + tg_hi) * 3 + 2) * (NH * HD) + h * HD + n0;
        float2 va = *(const float2*)vpa;
        float2 vb = *(const float2*)vpb;
        float2 oa = make_float2(o[j][0] + rem_lo * va.x, o[j][1] + rem_lo * va.y);
        float2 ob = make_float2(o[j][2] + rem_hi * vb.x, o[j][3] + rem_hi * vb.y);
        *(float2*)(out + (((size_t)b * S_LEN + tg_lo) * NH + h) * HD + n0) = oa;
        *(float2*)(out + (((size_t)b * S_LEN + tg_hi) * NH + h) * HD + n0) = ob;
    }
}

extern "C" void kernel_launch(void* const* d_in, const int* in_sizes, int n_in,
                              void* d_out, int out_size)
{
    const float* qkv = (const float*)d_in[0];
    float* out = (float*)d_out;

    cudaFuncSetAttribute(sb_attn_kernel,
                         cudaFuncAttributeMaxDynamicSharedMemorySize,
                         SMEM_FLOATS * sizeof(float));

    dim3 grid(S_LEN / 64, NH, 2);   // (32, 16, 2)
    sb_attn_kernel<<<grid, NTHR, SMEM_FLOATS * sizeof(float)>>>(qkv, out);
}